// round 3
// baseline (speedup 1.0000x reference)
#include <cuda_runtime.h>
#include <math.h>

// ---------------- problem constants ----------------
#define BATCH 2
#define TLEN 1024
#define DMODEL 2048
#define HKN 8
#define HVN 16
#define DKH 128
#define DVH 128
#define KWIN 4
#define KEY_DIM 1024
#define VALUE_DIM 2048
#define CONV_DIM 4096
#define MROWS (BATCH * TLEN)   // 2048

// ---------------- scratch (__device__ globals; no runtime allocation) ---
__device__ float g_mixed[MROWS * CONV_DIM];     // post qkv-proj, pre-conv
__device__ float g_q[MROWS * KEY_DIM];          // normalized+scaled q  [bt, hk, dk]
__device__ float g_k[MROWS * KEY_DIM];          // normalized k
__device__ float g_v[MROWS * VALUE_DIM];        // v                   [bt, hv, dv]
__device__ float g_z[MROWS * VALUE_DIM];        // z (raw, silu applied later)
__device__ float g_beta[MROWS * HVN];
__device__ float g_eg[MROWS * HVN];             // exp(g) decay factors
__device__ float g_o[MROWS * VALUE_DIM];        // recurrence output
__device__ float g_y[MROWS * VALUE_DIM];        // post-norm gated output

// ---------------- generic fp32 SIMT GEMM: C[M,N] = A[M,K] * B[K,N] ------
// All row-major. M,N multiples of 128; K multiple of 8 (true for our sizes).
// mode 0: A=Aext, C=g_mixed   (H @ W_qkv)
// mode 1: A=Aext, C=g_z       (H @ W_z)
// mode 2: A=g_y,  C=Cext      (y @ W_out)
#define GBM 128
#define GBN 128
#define GBK 8

__global__ __launch_bounds__(256, 2)
void gemm_f32(const float* __restrict__ Aext, const float* __restrict__ B,
              float* __restrict__ Cext, int M, int N, int K, int mode) {
    const float* A = (mode == 2) ? g_y : Aext;
    float* C = (mode == 0) ? g_mixed : (mode == 1) ? g_z : Cext;

    __shared__ __align__(16) float As[GBK][GBM];
    __shared__ __align__(16) float Bs[GBK][GBN];

    const int tid = threadIdx.x;
    const int bm = blockIdx.y * GBM;
    const int bn = blockIdx.x * GBN;

    // global->smem load mapping (one float4 per thread per tile, each matrix)
    const int arow  = tid >> 1;             // 0..127
    const int acol4 = (tid & 1) * 4;        // 0 or 4
    const int brow  = tid >> 5;             // 0..7
    const int bcol4 = (tid & 31) * 4;       // 0..124

    const float* Aptr = A + (size_t)(bm + arow) * K + acol4;
    const float* Bptr = B + (size_t)brow * N + bn + bcol4;

    const int tx = tid & 15;                // output col group
    const int ty = tid >> 4;                // output row group

    float acc[8][8];
#pragma unroll
    for (int i = 0; i < 8; i++)
#pragma unroll
        for (int j = 0; j < 8; j++) acc[i][j] = 0.f;

    const int nk = K / GBK;
    float4 ar = *(const float4*)Aptr;
    float4 br = *(const float4*)Bptr;

    for (int kt = 0; kt < nk; kt++) {
        // stage into shared (A transposed)
        As[acol4 + 0][arow] = ar.x;
        As[acol4 + 1][arow] = ar.y;
        As[acol4 + 2][arow] = ar.z;
        As[acol4 + 3][arow] = ar.w;
        *(float4*)&Bs[brow][bcol4] = br;
        __syncthreads();

        if (kt + 1 < nk) {
            ar = *(const float4*)(Aptr + (size_t)(kt + 1) * GBK);
            br = *(const float4*)(Bptr + (size_t)(kt + 1) * GBK * N);
        }

#pragma unroll
        for (int kk = 0; kk < GBK; kk++) {
            float a[8], b[8];
            *(float4*)&a[0] = *(const float4*)&As[kk][ty * 8];
            *(float4*)&a[4] = *(const float4*)&As[kk][ty * 8 + 4];
            *(float4*)&b[0] = *(const float4*)&Bs[kk][tx * 8];
            *(float4*)&b[4] = *(const float4*)&Bs[kk][tx * 8 + 4];
#pragma unroll
            for (int i = 0; i < 8; i++)
#pragma unroll
                for (int j = 0; j < 8; j++)
                    acc[i][j] = fmaf(a[i], b[j], acc[i][j]);
        }
        __syncthreads();
    }

    // write out
#pragma unroll
    for (int i = 0; i < 8; i++) {
        float* Crow = C + (size_t)(bm + ty * 8 + i) * N + bn + tx * 8;
        *(float4*)Crow       = make_float4(acc[i][0], acc[i][1], acc[i][2], acc[i][3]);
        *(float4*)(Crow + 4) = make_float4(acc[i][4], acc[i][5], acc[i][6], acc[i][7]);
    }
}

// ---------------- conv + silu + split + l2norm --------------------------
__global__ __launch_bounds__(512)
void conv_kernel(const float* __restrict__ conv_w) {
    const int bt = blockIdx.x;             // 0..2047
    const int b = bt >> 10;
    const int t = bt & 1023;
    __shared__ float y[CONV_DIM];
    __shared__ float rsq[16];

    const int tid = threadIdx.x;
    for (int c = tid; c < CONV_DIM; c += 512) {
        float acc = 0.f;
#pragma unroll
        for (int j = 0; j < KWIN; j++) {
            int tt = t - (KWIN - 1) + j;
            if (tt >= 0)
                acc = fmaf(conv_w[c * KWIN + j],
                           g_mixed[(size_t)(b * TLEN + tt) * CONV_DIM + c], acc);
        }
        y[c] = acc / (1.f + expf(-acc));   // silu
    }
    __syncthreads();

    // l2 norms for the first 2048 channels (q heads 0-7, k heads 0-7)
    const int w = tid >> 5, lane = tid & 31;   // 16 warps
    {
        float ss = 0.f;
#pragma unroll
        for (int i = 0; i < 4; i++) {
            float vv = y[w * 128 + lane + 32 * i];
            ss = fmaf(vv, vv, ss);
        }
#pragma unroll
        for (int off = 16; off > 0; off >>= 1)
            ss += __shfl_xor_sync(0xffffffffu, ss, off);
        if (lane == 0) rsq[w] = rsqrtf(ss + 1e-6f);
    }
    __syncthreads();

    const float QSCALE = 0.08838834764831845f;  // 128^-0.5
    for (int c = tid; c < CONV_DIM; c += 512) {
        float val = y[c];
        if (c < KEY_DIM) {
            g_q[(size_t)bt * KEY_DIM + c] = val * rsq[c >> 7] * QSCALE;
        } else if (c < 2 * KEY_DIM) {
            g_k[(size_t)bt * KEY_DIM + (c - KEY_DIM)] = val * rsq[c >> 7];
        } else {
            g_v[(size_t)bt * VALUE_DIM + (c - 2 * KEY_DIM)] = val;
        }
    }
}

// ---------------- beta / decay gates ------------------------------------
__global__ __launch_bounds__(256)
void gate_kernel(const float* __restrict__ hidden, const float* __restrict__ W_b,
                 const float* __restrict__ W_a, const float* __restrict__ dt_bias,
                 const float* __restrict__ A_log) {
    const int bt = blockIdx.x;
    const int w = threadIdx.x >> 5, lane = threadIdx.x & 31;
    const float* h = hidden + (size_t)bt * DMODEL;

    for (int d = w * 4; d < w * 4 + 4; d++) {    // 32 dots: 16 beta + 16 g
        const int hh = d & 15;
        const bool isA = d >= 16;
        const float* W = isA ? W_a : W_b;
        float s = 0.f;
        for (int i = lane; i < DMODEL; i += 32)
            s = fmaf(h[i], W[(size_t)i * HVN + hh], s);
#pragma unroll
        for (int off = 16; off > 0; off >>= 1)
            s += __shfl_xor_sync(0xffffffffu, s, off);
        if (lane == 0) {
            if (!isA) {
                g_beta[(size_t)bt * HVN + hh] = 1.f / (1.f + expf(-s));
            } else {
                float x = s + dt_bias[hh];
                float sp = (x > 20.f) ? x : log1pf(expf(x));
                g_eg[(size_t)bt * HVN + hh] = expf(-expf(A_log[hh]) * sp);
            }
        }
    }
}

// ---------------- gated delta-rule scan ---------------------------------
// grid: BATCH*HVN*4 = 128 blocks, 128 threads.
// block -> (b,h, column-split of 32). thread quad (sub=tid&3) splits 128 rows.
#define NSPLIT 4
__global__ __launch_bounds__(128)
void scan_kernel() {
    const int blk = blockIdx.x;
    const int split = blk & (NSPLIT - 1);
    const int bh = blk >> 2;          // 0..31
    const int b = bh >> 4;
    const int h = bh & 15;
    const int hk = h >> 1;            // GQA repeat_interleave: source head = h / 2

    const int tid = threadIdx.x;
    const int sub = tid & 3;          // row group 0..3  (rows sub*32 .. +31)
    const int colw = tid >> 2;        // 0..31
    const int col = split * 32 + colw;

    // padded shared staging: 4 segments of 32, stride 36 -> conflict-free
    __shared__ __align__(16) float ksh[2][144];
    __shared__ __align__(16) float qsh[2][144];
    const int lpos = (tid >> 5) * 36 + (tid & 31);

    float S[32];
#pragma unroll
    for (int i = 0; i < 32; i++) S[i] = 0.f;

    const float* kb = g_k + ((size_t)(b * TLEN) * HKN + hk) * DKH;  // +t*1024
    const float* qb = g_q + ((size_t)(b * TLEN) * HKN + hk) * DKH;
    const float* vb = g_v + ((size_t)(b * TLEN) * HVN + h) * DVH + col;  // +t*2048
    const float* egb = g_eg + (size_t)(b * TLEN) * HVN + h;              // +t*16
    const float* btb = g_beta + (size_t)(b * TLEN) * HVN + h;
    float* ob = g_o + ((size_t)(b * TLEN) * HVN + h) * DVH + col;

    // prologue: load t=0
    float kr = kb[tid];
    float qr = qb[tid];
    float vr = vb[0];
    float egr = egb[0];
    float btr = btb[0];

    int cur = 0;
    for (int t = 0; t < TLEN; t++) {
        // stage current step into shared, latch scalars
        ksh[cur][lpos] = kr;
        qsh[cur][lpos] = qr;
        const float vc = vr, egc = egr, btc = btr;
        __syncthreads();

        // prefetch next step
        if (t + 1 < TLEN) {
            kr = kb[(size_t)(t + 1) * (HKN * DKH) + tid];
            qr = qb[(size_t)(t + 1) * (HKN * DKH) + tid];
            vr = vb[(size_t)(t + 1) * (HVN * DVH)];
            egr = egb[(size_t)(t + 1) * HVN];
            btr = btb[(size_t)(t + 1) * HVN];
        }

        // load row-slices of k and q for this thread
        float kf[32], qf[32];
        const float* kp = &ksh[cur][sub * 36];
        const float* qp = &qsh[cur][sub * 36];
#pragma unroll
        for (int i = 0; i < 32; i += 4) {
            float4 x = *(const float4*)(kp + i);
            kf[i] = x.x; kf[i + 1] = x.y; kf[i + 2] = x.z; kf[i + 3] = x.w;
            float4 yq = *(const float4*)(qp + i);
            qf[i] = yq.x; qf[i + 1] = yq.y; qf[i + 2] = yq.z; qf[i + 3] = yq.w;
        }

        // kS (over old state), factor the decay out of the dot
        float p = 0.f;
#pragma unroll
        for (int i = 0; i < 32; i++) p = fmaf(kf[i], S[i], p);
        p += __shfl_xor_sync(0xffffffffu, p, 1);
        p += __shfl_xor_sync(0xffffffffu, p, 2);

        const float va = (vc - egc * p) * btc;

        // S = eg*S + k (x) va;  o = q . S_new
        float op = 0.f;
#pragma unroll
        for (int i = 0; i < 32; i++) {
            S[i] = fmaf(S[i], egc, kf[i] * va);
            op = fmaf(qf[i], S[i], op);
        }
        op += __shfl_xor_sync(0xffffffffu, op, 1);
        op += __shfl_xor_sync(0xffffffffu, op, 2);
        if (sub == 0) ob[(size_t)t * (HVN * DVH)] = op;

        cur ^= 1;
    }
}

// ---------------- gated RMSNorm * silu(z) -------------------------------
__global__ __launch_bounds__(256)
void norm_kernel(const float* __restrict__ nw) {
    const int gw = blockIdx.x * 8 + (threadIdx.x >> 5);  // (bt,h) index
    const int lane = threadIdx.x & 31;
    const int bt = gw >> 4;
    const int h = gw & 15;

    const float* op = g_o + (size_t)gw * DVH;
    const float* zp = g_z + (size_t)bt * VALUE_DIM + h * DVH;

    float vv[4];
    float ss = 0.f;
#pragma unroll
    for (int i = 0; i < 4; i++) {
        vv[i] = op[lane + 32 * i];
        ss = fmaf(vv[i], vv[i], ss);
    }
#pragma unroll
    for (int off = 16; off > 0; off >>= 1)
        ss += __shfl_xor_sync(0xffffffffu, ss, off);

    const float r = rsqrtf(ss * (1.f / 128.f) + 1e-6f);
#pragma unroll
    for (int i = 0; i < 4; i++) {
        int d = lane + 32 * i;
        float zz = zp[d];
        float sil = zz / (1.f + expf(-zz));
        g_y[(size_t)bt * VALUE_DIM + h * DVH + d] = vv[i] * r * nw[d] * sil;
    }
}

// ---------------- launch (no runtime API calls besides kernel launches) --
extern "C" void kernel_launch(void* const* d_in, const int* in_sizes, int n_in,
                              void* d_out, int out_size) {
    (void)in_sizes; (void)n_in; (void)out_size;
    const float* hidden  = (const float*)d_in[0];
    const float* W_qkv   = (const float*)d_in[1];
    const float* W_z     = (const float*)d_in[2];
    const float* W_b     = (const float*)d_in[3];
    const float* W_a     = (const float*)d_in[4];
    const float* conv_w  = (const float*)d_in[5];
    const float* dt_bias = (const float*)d_in[6];
    const float* A_log   = (const float*)d_in[7];
    const float* norm_w  = (const float*)d_in[8];
    const float* W_out   = (const float*)d_in[9];
    float* out = (float*)d_out;

    // 1) mixed = H @ W_qkv     (C = g_mixed, mode 0)
    gemm_f32<<<dim3(CONV_DIM / GBN, MROWS / GBM), 256>>>(hidden, W_qkv, nullptr,
                                                         MROWS, CONV_DIM, DMODEL, 0);
    // 2) causal conv + silu + split + l2norm(q,k)
    conv_kernel<<<MROWS, 512>>>(conv_w);
    // 3) z = H @ W_z           (C = g_z, mode 1)
    gemm_f32<<<dim3(VALUE_DIM / GBN, MROWS / GBM), 256>>>(hidden, W_z, nullptr,
                                                          MROWS, VALUE_DIM, DMODEL, 1);
    // 4) beta / exp(g)
    gate_kernel<<<MROWS, 256>>>(hidden, W_b, W_a, dt_bias, A_log);
    // 5) gated delta-rule recurrence
    scan_kernel<<<BATCH * HVN * NSPLIT, 128>>>();
    // 6) gated RMSNorm * silu(z)
    norm_kernel<<<MROWS * HVN / 8, 256>>>(norm_w);
    // 7) out = y @ W_out       (A = g_y, mode 2)
    gemm_f32<<<dim3(DMODEL / GBN, MROWS / GBM), 256>>>(nullptr, W_out, out,
                                                       MROWS, DMODEL, VALUE_DIM, 2);
}

// round 5
// speedup vs baseline: 1.4638x; 1.4638x over previous
#include <cuda_runtime.h>
#include <cuda_bf16.h>
#include <math.h>
#include <stdint.h>

// ---------------- problem constants ----------------
#define BATCH 2
#define TLEN 1024
#define DMODEL 2048
#define HKN 8
#define HVN 16
#define DKH 128
#define DVH 128
#define KWIN 4
#define KEY_DIM 1024
#define VALUE_DIM 2048
#define CONV_DIM 4096
#define MROWS (BATCH * TLEN)   // 2048

// ---------------- scratch (__device__ globals) --------------------------
__device__ float g_mixed[MROWS * CONV_DIM];
__device__ float g_q[MROWS * KEY_DIM];
__device__ float g_k[MROWS * KEY_DIM];
__device__ float g_v[MROWS * VALUE_DIM];
__device__ float g_z[MROWS * VALUE_DIM];
__device__ float g_beta[MROWS * HVN];
__device__ float g_eg[MROWS * HVN];
__device__ float g_o[MROWS * VALUE_DIM];

// bf16 hi/lo splits
__device__ __align__(16) __nv_bfloat16 gh_hi[MROWS * DMODEL];
__device__ __align__(16) __nv_bfloat16 gh_lo[MROWS * DMODEL];
__device__ __align__(16) __nv_bfloat16 gy_hi[MROWS * VALUE_DIM];
__device__ __align__(16) __nv_bfloat16 gy_lo[MROWS * VALUE_DIM];
// transposed weights: [N][K=2048]
__device__ __align__(16) __nv_bfloat16 wq_hi[CONV_DIM * DMODEL];
__device__ __align__(16) __nv_bfloat16 wq_lo[CONV_DIM * DMODEL];
__device__ __align__(16) __nv_bfloat16 wz_hi[VALUE_DIM * DMODEL];
__device__ __align__(16) __nv_bfloat16 wz_lo[VALUE_DIM * DMODEL];
__device__ __align__(16) __nv_bfloat16 wo_hi[DMODEL * VALUE_DIM];
__device__ __align__(16) __nv_bfloat16 wo_lo[DMODEL * VALUE_DIM];

// ---------------- helpers ----------------------------------------------
__device__ __forceinline__ uint32_t smem_u32(const void* p) {
    uint32_t a;
    asm("{ .reg .u64 t; cvta.to.shared.u64 t, %1; cvt.u32.u64 %0, t; }"
        : "=r"(a) : "l"(p));
    return a;
}

#define CP_ASYNC16(sa, ga) \
    asm volatile("cp.async.cg.shared.global [%0], [%1], 16;" \
                 :: "r"(sa), "l"(ga) : "memory")
#define CP_COMMIT() asm volatile("cp.async.commit_group;" ::: "memory")
#define CP_WAIT1()  asm volatile("cp.async.wait_group 1;" ::: "memory")

#define LDSM_X4(r, a) \
    asm volatile("ldmatrix.sync.aligned.m8n8.x4.shared.b16 {%0,%1,%2,%3}, [%4];" \
                 : "=r"((r)[0]), "=r"((r)[1]), "=r"((r)[2]), "=r"((r)[3]) \
                 : "r"(a))

#define MMA16816(c, a, b) \
    asm volatile("mma.sync.aligned.m16n8k16.row.col.f32.bf16.bf16.f32 " \
                 "{%0,%1,%2,%3}, {%4,%5,%6,%7}, {%8,%9}, {%0,%1,%2,%3};" \
                 : "+f"((c)[0]), "+f"((c)[1]), "+f"((c)[2]), "+f"((c)[3]) \
                 : "r"((a)[0]), "r"((a)[1]), "r"((a)[2]), "r"((a)[3]), \
                   "r"((b)[0]), "r"((b)[1]))

// ---------------- split kernels ----------------------------------------
__global__ __launch_bounds__(256)
void hsplit_kernel(const float* __restrict__ src) {
    size_t i = ((size_t)blockIdx.x * 256 + threadIdx.x) * 4;
    float4 v = *(const float4*)&src[i];
    float f[4] = {v.x, v.y, v.z, v.w};
#pragma unroll
    for (int j = 0; j < 4; j++) {
        __nv_bfloat16 hi = __float2bfloat16(f[j]);
        gh_hi[i + j] = hi;
        gh_lo[i + j] = __float2bfloat16(f[j] - __bfloat162float(hi));
    }
}

// src [2048][N] fp32 -> dst [N][2048] bf16 hi/lo (transpose + split)
__global__ __launch_bounds__(256)
void wsplit_kernel(const float* __restrict__ src, int Ncols, int which) {
    __nv_bfloat16 *dh, *dl;
    if (which == 0) { dh = wq_hi; dl = wq_lo; }
    else if (which == 1) { dh = wz_hi; dl = wz_lo; }
    else { dh = wo_hi; dl = wo_lo; }

    __shared__ float tile[32][33];
    const int tx = threadIdx.x & 31, ty = threadIdx.x >> 5;
    const int bx = blockIdx.x, by = blockIdx.y;
#pragma unroll
    for (int j = 0; j < 4; j++)
        tile[ty + j * 8][tx] =
            src[(size_t)(by * 32 + ty + j * 8) * Ncols + bx * 32 + tx];
    __syncthreads();
#pragma unroll
    for (int j = 0; j < 4; j++) {
        float v = tile[tx][ty + j * 8];
        __nv_bfloat16 hi = __float2bfloat16(v);
        size_t idx = (size_t)(bx * 32 + ty + j * 8) * 2048 + by * 32 + tx;
        dh[idx] = hi;
        dl[idx] = __float2bfloat16(v - __bfloat162float(hi));
    }
}

// ---------------- mma.sync bf16x3 GEMM ----------------------------------
// C[M,N] = A[M,2048] @ Bt[N,2048]^T, fp32 out.
// CTA tile 128x128, BK=32, 3-stage cp.async pipeline, 8 warps (2m x 4n),
// warp tile 64x32. Row pad 80B -> ldmatrix conflict-free.
#define MAT_BYTES 10240            // 128 rows * 80B
#define STG_BYTES (4 * MAT_BYTES)  // Ahi, Alo, Bhi, Blo
#define NSTAGE 3
#define GEMM_SMEM (NSTAGE * STG_BYTES)

__global__ __launch_bounds__(256, 1)
void gemm_mma(float* __restrict__ Cext, int N, int mode) {
    extern __shared__ char sm[];
    const uint32_t sbase = smem_u32(sm);
    const int tid = threadIdx.x;
    const int wid = tid >> 5, lane = tid & 31;
    const int bn = blockIdx.x * 128, bm = blockIdx.y * 128;
    const int warp_m = (wid >> 2) * 64, warp_n = (wid & 3) * 32;

    const __nv_bfloat16 *gAh, *gAl, *gBh, *gBl;
    float* C;
    if (mode == 0) {
        gAh = gh_hi; gAl = gh_lo; gBh = wq_hi; gBl = wq_lo; C = g_mixed;
    } else if (mode == 1) {
        gAh = gh_hi; gAl = gh_lo; gBh = wz_hi; gBl = wz_lo; C = g_z;
    } else {
        gAh = gy_hi; gAl = gy_lo; gBh = wo_hi; gBl = wo_lo; C = Cext;
    }
    const __nv_bfloat16* gsrc[4] = {gAh, gAl, gBh, gBl};

    // per-thread load mapping: 2 x 16B per matrix per stage
    const int lrow = tid >> 1;            // 0..127
    const int lq0 = (tid & 1) * 2;        // 0 or 2

    auto issue = [&](int kc, int st) {
        const uint32_t stb = sbase + (uint32_t)st * STG_BYTES;
#pragma unroll
        for (int m = 0; m < 4; m++) {
            const int rb = (m < 2) ? bm : bn;
            const __nv_bfloat16* gp =
                gsrc[m] + (size_t)(rb + lrow) * 2048 + kc * 32 + lq0 * 8;
            const uint32_t sa = stb + (uint32_t)m * MAT_BYTES + lrow * 80 + lq0 * 16;
            CP_ASYNC16(sa, gp);
            CP_ASYNC16(sa + 16, gp + 8);
        }
    };

    float acc[4][4][4];
#pragma unroll
    for (int i = 0; i < 4; i++)
#pragma unroll
        for (int j = 0; j < 4; j++)
#pragma unroll
            for (int r = 0; r < 4; r++) acc[i][j][r] = 0.f;

    // prologue: 2 stages in flight
    issue(0, 0); CP_COMMIT();
    issue(1, 1); CP_COMMIT();

    // precomputed ldmatrix lane addressing pieces
    const int a_row = lane & 15;          // A matrix row within frag
    const int a_kg = (lane >> 4) * 16;    // 16B k-group
    const int b_row = (lane & 7) + ((lane >> 3) & 1) * 8;
    const int b_kg = (lane >> 4) * 16;

    for (int kc = 0; kc < 64; kc++) {
        CP_WAIT1();
        __syncthreads();

        const uint32_t stb = sbase + (uint32_t)(kc % NSTAGE) * STG_BYTES;
        const uint32_t As_h = stb;
        const uint32_t As_l = stb + MAT_BYTES;
        const uint32_t Bs_h = stb + 2 * MAT_BYTES;
        const uint32_t Bs_l = stb + 3 * MAT_BYTES;

#pragma unroll
        for (int k16 = 0; k16 < 2; k16++) {
            const int kb = k16 * 32;
            uint32_t ah[4][4], al[4][4], bh[4][2], bl[4][2];
#pragma unroll
            for (int f = 0; f < 4; f++) {
                uint32_t ra = (warp_m + f * 16 + a_row) * 80 + kb + a_kg;
                LDSM_X4(ah[f], As_h + ra);
                LDSM_X4(al[f], As_l + ra);
            }
#pragma unroll
            for (int p = 0; p < 2; p++) {
                uint32_t rb8 = (warp_n + p * 16 + b_row) * 80 + kb + b_kg;
                uint32_t r[4];
                LDSM_X4(r, Bs_h + rb8);
                bh[2 * p][0] = r[0]; bh[2 * p][1] = r[2];
                bh[2 * p + 1][0] = r[1]; bh[2 * p + 1][1] = r[3];
                LDSM_X4(r, Bs_l + rb8);
                bl[2 * p][0] = r[0]; bl[2 * p][1] = r[2];
                bl[2 * p + 1][0] = r[1]; bl[2 * p + 1][1] = r[3];
            }
#pragma unroll
            for (int mi = 0; mi < 4; mi++)
#pragma unroll
                for (int ni = 0; ni < 4; ni++) {
                    MMA16816(acc[mi][ni], ah[mi], bh[ni]);
                    MMA16816(acc[mi][ni], ah[mi], bl[ni]);
                    MMA16816(acc[mi][ni], al[mi], bh[ni]);
                }
        }

        if (kc + 2 < 64) issue(kc + 2, (kc + 2) % NSTAGE);
        CP_COMMIT();
    }

    // epilogue: thread t of warp holds C rows (mi*16 + lane/4 [+8]),
    // cols ni*8 + 2*(lane%4) + {0,1}
    const int er = lane >> 2, ec = (lane & 3) * 2;
#pragma unroll
    for (int mi = 0; mi < 4; mi++) {
#pragma unroll
        for (int ni = 0; ni < 4; ni++) {
            float* c0 = C + (size_t)(bm + warp_m + mi * 16 + er) * N +
                        bn + warp_n + ni * 8 + ec;
            *(float2*)c0 = make_float2(acc[mi][ni][0], acc[mi][ni][1]);
            *(float2*)(c0 + 8 * (size_t)N) =
                make_float2(acc[mi][ni][2], acc[mi][ni][3]);
        }
    }
}

// ---------------- conv + silu + split + l2norm --------------------------
__global__ __launch_bounds__(512)
void conv_kernel(const float* __restrict__ conv_w) {
    const int bt = blockIdx.x;
    const int b = bt >> 10;
    const int t = bt & 1023;
    __shared__ float y[CONV_DIM];
    __shared__ float rsq[16];

    const int tid = threadIdx.x;
    for (int c = tid; c < CONV_DIM; c += 512) {
        float acc = 0.f;
#pragma unroll
        for (int j = 0; j < KWIN; j++) {
            int tt = t - (KWIN - 1) + j;
            if (tt >= 0)
                acc = fmaf(conv_w[c * KWIN + j],
                           g_mixed[(size_t)(b * TLEN + tt) * CONV_DIM + c], acc);
        }
        y[c] = acc / (1.f + expf(-acc));
    }
    __syncthreads();

    const int w = tid >> 5, lane = tid & 31;
    {
        float ss = 0.f;
#pragma unroll
        for (int i = 0; i < 4; i++) {
            float vv = y[w * 128 + lane + 32 * i];
            ss = fmaf(vv, vv, ss);
        }
#pragma unroll
        for (int off = 16; off > 0; off >>= 1)
            ss += __shfl_xor_sync(0xffffffffu, ss, off);
        if (lane == 0) rsq[w] = rsqrtf(ss + 1e-6f);
    }
    __syncthreads();

    const float QSCALE = 0.08838834764831845f;
    for (int c = tid; c < CONV_DIM; c += 512) {
        float val = y[c];
        if (c < KEY_DIM) {
            g_q[(size_t)bt * KEY_DIM + c] = val * rsq[c >> 7] * QSCALE;
        } else if (c < 2 * KEY_DIM) {
            g_k[(size_t)bt * KEY_DIM + (c - KEY_DIM)] = val * rsq[c >> 7];
        } else {
            g_v[(size_t)bt * VALUE_DIM + (c - 2 * KEY_DIM)] = val;
        }
    }
}

// ---------------- gate mini-GEMM: M-tile 32 x N 32 ----------------------
__global__ __launch_bounds__(256)
void gate2_kernel(const float* __restrict__ hidden, const float* __restrict__ W_b,
                  const float* __restrict__ W_a, const float* __restrict__ dt_bias,
                  const float* __restrict__ A_log) {
    __shared__ float hs[32][68];
    __shared__ float ws[64][33];
    const int tid = threadIdx.x;
    const int mb = blockIdx.x * 32;
    const int mi = tid >> 3;
    const int c4 = (tid & 7) * 4;
    float a0 = 0.f, a1 = 0.f, a2 = 0.f, a3 = 0.f;

    for (int kc = 0; kc < DMODEL; kc += 64) {
#pragma unroll
        for (int l = 0; l < 2; l++) {
            int t = tid + l * 256;
            int r = t >> 4, cc = (t & 15) * 4;
            *(float4*)&hs[r][cc] =
                *(const float4*)&hidden[(size_t)(mb + r) * DMODEL + kc + cc];
        }
#pragma unroll
        for (int l = 0; l < 8; l++) {
            int t = tid + l * 256;
            int r = t >> 5, cc = t & 31;
            ws[r][cc] = (cc < 16) ? W_b[(size_t)(kc + r) * HVN + cc]
                                  : W_a[(size_t)(kc + r) * HVN + cc - 16];
        }
        __syncthreads();
#pragma unroll
        for (int k = 0; k < 64; k++) {
            float a = hs[mi][k];
            a0 = fmaf(a, ws[k][c4 + 0], a0);
            a1 = fmaf(a, ws[k][c4 + 1], a1);
            a2 = fmaf(a, ws[k][c4 + 2], a2);
            a3 = fmaf(a, ws[k][c4 + 3], a3);
        }
        __syncthreads();
    }
    float accs[4] = {a0, a1, a2, a3};
    const int m = mb + mi;
#pragma unroll
    for (int j = 0; j < 4; j++) {
        int c = c4 + j;
        float s = accs[j];
        if (c < 16) {
            g_beta[(size_t)m * HVN + c] = 1.f / (1.f + expf(-s));
        } else {
            int hh = c - 16;
            float x = s + dt_bias[hh];
            float sp = (x > 20.f) ? x : log1pf(expf(x));
            g_eg[(size_t)m * HVN + hh] = expf(-expf(A_log[hh]) * sp);
        }
    }
}

// ---------------- gated delta-rule scan ---------------------------------
#define NSPLIT 4
__global__ __launch_bounds__(128)
void scan_kernel() {
    const int blk = blockIdx.x;
    const int split = blk & (NSPLIT - 1);
    const int bh = blk >> 2;
    const int b = bh >> 4;
    const int h = bh & 15;
    const int hk = h >> 1;

    const int tid = threadIdx.x;
    const int sub = tid & 3;
    const int colw = tid >> 2;
    const int col = split * 32 + colw;

    __shared__ __align__(16) float ksh[2][144];
    __shared__ __align__(16) float qsh[2][144];
    const int lpos = (tid >> 5) * 36 + (tid & 31);

    float S[32];
#pragma unroll
    for (int i = 0; i < 32; i++) S[i] = 0.f;

    const float* kb = g_k + ((size_t)(b * TLEN) * HKN + hk) * DKH;
    const float* qb = g_q + ((size_t)(b * TLEN) * HKN + hk) * DKH;
    const float* vb = g_v + ((size_t)(b * TLEN) * HVN + h) * DVH + col;
    const float* egb = g_eg + (size_t)(b * TLEN) * HVN + h;
    const float* btb = g_beta + (size_t)(b * TLEN) * HVN + h;
    float* ob = g_o + ((size_t)(b * TLEN) * HVN + h) * DVH + col;

    float kr = kb[tid];
    float qr = qb[tid];
    float vr = vb[0];
    float egr = egb[0];
    float btr = btb[0];

    int cur = 0;
    for (int t = 0; t < TLEN; t++) {
        ksh[cur][lpos] = kr;
        qsh[cur][lpos] = qr;
        const float vc = vr, egc = egr, btc = btr;
        __syncthreads();

        if (t + 1 < TLEN) {
            kr = kb[(size_t)(t + 1) * (HKN * DKH) + tid];
            qr = qb[(size_t)(t + 1) * (HKN * DKH) + tid];
            vr = vb[(size_t)(t + 1) * (HVN * DVH)];
            egr = egb[(size_t)(t + 1) * HVN];
            btr = btb[(size_t)(t + 1) * HVN];
        }

        float kf[32], qf[32];
        const float* kp = &ksh[cur][sub * 36];
        const float* qp = &qsh[cur][sub * 36];
#pragma unroll
        for (int i = 0; i < 32; i += 4) {
            float4 x = *(const float4*)(kp + i);
            kf[i] = x.x; kf[i + 1] = x.y; kf[i + 2] = x.z; kf[i + 3] = x.w;
            float4 yq = *(const float4*)(qp + i);
            qf[i] = yq.x; qf[i + 1] = yq.y; qf[i + 2] = yq.z; qf[i + 3] = yq.w;
        }

        float p = 0.f;
#pragma unroll
        for (int i = 0; i < 32; i++) p = fmaf(kf[i], S[i], p);
        p += __shfl_xor_sync(0xffffffffu, p, 1);
        p += __shfl_xor_sync(0xffffffffu, p, 2);

        const float va = (vc - egc * p) * btc;

        float op = 0.f;
#pragma unroll
        for (int i = 0; i < 32; i++) {
            S[i] = fmaf(S[i], egc, kf[i] * va);
            op = fmaf(qf[i], S[i], op);
        }
        op += __shfl_xor_sync(0xffffffffu, op, 1);
        op += __shfl_xor_sync(0xffffffffu, op, 2);
        if (sub == 0) ob[(size_t)t * (HVN * DVH)] = op;

        cur ^= 1;
    }
}

// ---------------- gated RMSNorm * silu(z) -> bf16 hi/lo splits ----------
__global__ __launch_bounds__(256)
void norm_kernel(const float* __restrict__ nw) {
    const int gw = blockIdx.x * 8 + (threadIdx.x >> 5);
    const int lane = threadIdx.x & 31;
    const int bt = gw >> 4;
    const int h = gw & 15;

    const float* op = g_o + (size_t)gw * DVH;
    const float* zp = g_z + (size_t)bt * VALUE_DIM + h * DVH;

    float vv[4];
    float ss = 0.f;
#pragma unroll
    for (int i = 0; i < 4; i++) {
        vv[i] = op[lane + 32 * i];
        ss = fmaf(vv[i], vv[i], ss);
    }
#pragma unroll
    for (int off = 16; off > 0; off >>= 1)
        ss += __shfl_xor_sync(0xffffffffu, ss, off);

    const float r = rsqrtf(ss * (1.f / 128.f) + 1e-6f);
#pragma unroll
    for (int i = 0; i < 4; i++) {
        int d = lane + 32 * i;
        float zz = zp[d];
        float sil = zz / (1.f + expf(-zz));
        float yv = vv[i] * r * nw[d] * sil;
        size_t idx = (size_t)bt * VALUE_DIM + h * DVH + d;
        __nv_bfloat16 hi = __float2bfloat16(yv);
        gy_hi[idx] = hi;
        gy_lo[idx] = __float2bfloat16(yv - __bfloat162float(hi));
    }
}

// ---------------- launch ------------------------------------------------
extern "C" void kernel_launch(void* const* d_in, const int* in_sizes, int n_in,
                              void* d_out, int out_size) {
    (void)in_sizes; (void)n_in; (void)out_size;
    const float* hidden  = (const float*)d_in[0];
    const float* W_qkv   = (const float*)d_in[1];
    const float* W_z     = (const float*)d_in[2];
    const float* W_b     = (const float*)d_in[3];
    const float* W_a     = (const float*)d_in[4];
    const float* conv_w  = (const float*)d_in[5];
    const float* dt_bias = (const float*)d_in[6];
    const float* A_log   = (const float*)d_in[7];
    const float* norm_w  = (const float*)d_in[8];
    const float* W_out   = (const float*)d_in[9];
    float* out = (float*)d_out;

    // opt-in to >48KB dynamic smem (no allocation; idempotent)
    cudaFuncSetAttribute(gemm_mma, cudaFuncAttributeMaxDynamicSharedMemorySize,
                         GEMM_SMEM);

    // 0) splits: weights (transpose) + hidden
    wsplit_kernel<<<dim3(CONV_DIM / 32, DMODEL / 32), 256>>>(W_qkv, CONV_DIM, 0);
    wsplit_kernel<<<dim3(VALUE_DIM / 32, DMODEL / 32), 256>>>(W_z, VALUE_DIM, 1);
    wsplit_kernel<<<dim3(DMODEL / 32, VALUE_DIM / 32), 256>>>(W_out, DMODEL, 2);
    hsplit_kernel<<<(MROWS * DMODEL) / 1024, 256>>>(hidden);

    // 1) mixed = H @ W_qkv  (mma.sync bf16x3)
    gemm_mma<<<dim3(CONV_DIM / 128, MROWS / 128), 256, GEMM_SMEM>>>(nullptr, CONV_DIM, 0);
    // 2) conv + silu + split + l2norm
    conv_kernel<<<MROWS, 512>>>(conv_w);
    // 3) z = H @ W_z
    gemm_mma<<<dim3(VALUE_DIM / 128, MROWS / 128), 256, GEMM_SMEM>>>(nullptr, VALUE_DIM, 1);
    // 4) beta / exp(g)
    gate2_kernel<<<MROWS / 32, 256>>>(hidden, W_b, W_a, dt_bias, A_log);
    // 5) recurrence
    scan_kernel<<<BATCH * HVN * NSPLIT, 128>>>();
    // 6) gated RMSNorm * silu(z) -> gy splits
    norm_kernel<<<MROWS * HVN / 8, 256>>>(norm_w);
    // 7) out = y @ W_out
    gemm_mma<<<dim3(DMODEL / 128, MROWS / 128), 256, GEMM_SMEM>>>(out, DMODEL, 2);
}